// round 1
// baseline (speedup 1.0000x reference)
#include <cuda_runtime.h>
#include <math.h>

#define NMODES   6400
#define MDIM     80
#define NCHUNK   8
#define CHUNK    (NMODES / NCHUNK)
#define MAX_T    24576

#define KF   ((float)(1.0 / 44100.0))          /* fl32(K) */
#define K2F  ((float)((1.0/44100.0)*(1.0/44100.0)))

// mode params: x=theta(=fl(omega*K)), y=sigma, z=coef, w=unused
__device__ float4   g_modes[NMODES];
__device__ float    g_part[NCHUNK][MAX_T];
__device__ float    g_ir[MAX_T];
__device__ unsigned g_maxbits;

// ---------------------------------------------------------------------------
// Accurate float sine, flag-proof (explicit RN intrinsics). Valid |x| < ~1.2e5.
// Cody-Waite 4-term pi reduction with low-bit-count parts so n*part is exact
// for n up to ~33k, then SLEEF-style deg-9 minimax on [-pi/2, pi/2].
// ---------------------------------------------------------------------------
__device__ __forceinline__ float sin_acc(float x) {
    const float INV_PI = 0.318309886183790671538f;
    float nf = rintf(__fmul_rn(x, INV_PI));
    int   ni = (int)nf;
    // pi = H + M + L + LL ;  H: 8-bit mant, M: 9-bit, L: 9-bit  -> exact products
    float r = __fmaf_rn(-nf, 3.140625f, x);                     // exact
    r = __fmaf_rn(-nf, 9.670257568359375e-4f, r);               // exact
    r = __fmaf_rn(-nf, 6.2771141529083252e-7f, r);
    r = __fmaf_rn(-nf, 1.2154201256553420e-10f, r);
    float r2 = __fmul_rn(r, r);
    float p  = __fmaf_rn(2.60831598097865935e-06f, r2, -1.98106907191686332e-4f);
    p = __fmaf_rn(p, r2,  8.33307858556509018e-3f);
    p = __fmaf_rn(p, r2, -0.166666597127914429f);
    float s = __fmaf_rn(__fmul_rn(r, r2), p, r);
    return (ni & 1) ? -s : s;
}

__device__ __forceinline__ double softplus_d(double x) {
    return (x > 0.0) ? x + log1p(exp(-x)) : log1p(exp(x));
}
__device__ __forceinline__ float sigmoid_of(float argf) {
    return (float)(1.0 / (1.0 + exp(-(double)argf)));
}

// ---------------------------------------------------------------------------
// k0: per-mode parameter setup (6400 threads). Phase-critical chain done with
// explicit f32 RN ops to mirror the reference's float32 rounding sequence.
// ---------------------------------------------------------------------------
__global__ void k0_setup(const float* __restrict__ mu_raw,
                         const float* __restrict__ D_raw,
                         const float* __restrict__ T0_raw,
                         const float* __restrict__ Ly_raw,
                         const float* __restrict__ xo_raw,
                         const float* __restrict__ yo_raw) {
    int m = blockIdx.x * blockDim.x + threadIdx.x;
    if (m == 0) g_maxbits = 0u;
    if (m >= NMODES) return;

    // ---- scalar transforms (double -> correctly rounded f32) ----
    float mu  = __fadd_rn((float)softplus_d((double)*mu_raw),  1e-4f);
    float Dm  = __fadd_rn((float)softplus_d((double)*D_raw),   1e-4f);
    float T0m = __fadd_rn((float)softplus_d((double)*T0_raw),  1e-4f);

    float hLy = __fmul_rn(__fadd_rn((float)tanh((double)*Ly_raw), 1.0f), 0.5f);
    float Ly  = __fadd_rn(1.1f, __fmul_rn(2.9f, hLy));
    float hx  = __fmul_rn(__fadd_rn((float)tanh((double)*xo_raw), 1.0f), 0.5f);
    float xo  = __fadd_rn(0.49f, __fmul_rn(0.51f, hx));
    float hy  = __fmul_rn(__fadd_rn((float)tanh((double)*yo_raw), 1.0f), 0.5f);
    float yo  = __fadd_rn(__fmul_rn(0.51f, Ly), __fmul_rn(__fmul_rn(0.49f, Ly), hy));
    float yi  = __fmul_rn(0.467f, Ly);

    int mi = m / MDIM + 1;   // M_VEC (meshgrid 'ij')
    int nj = m % MDIM + 1;   // N_VEC
    const float PIf = (float)M_PI;   // np.float32(pi)

    // ---- phase-critical: g1 -> omega -> theta, explicit f32 RN chain ----
    float mf = (float)mi, nf = (float)nj;
    float t1 = __fmul_rn(mf, PIf);                       // / LX(=1) exact
    float t2 = __fdiv_rn(__fmul_rn(nf, PIf), Ly);
    float g1 = __fadd_rn(__fmul_rn(t1, t1), __fmul_rn(t2, t2));
    float om_sq = __fadd_rn(__fmul_rn(T0m, g1),
                            __fmul_rn(__fmul_rn(Dm, g1), g1));
    float omega = __fsqrt_rn(fmaxf(om_sq, 0.0f));
    float theta = __fmul_rn(omega, KF);                  // fl32(omega*K)

    // ---- damping ----
    const double OM2d   = 2.0 * M_PI * 500.0;
    const double DOMSQd = OM2d * OM2d;
    const double ALPHAd = 3.0 * log(10.0) / DOMSQd * (DOMSQd / 6.0);
    const double BETAd  = 3.0 * log(10.0) / DOMSQd * (1.0 / 2.0 - 1.0 / 6.0);
    float om2f  = __fmul_rn(omega, omega);
    float sigma = __fadd_rn((float)ALPHAd, __fmul_rn((float)BETAd, om2f));

    // ---- validity window (amplitude-only) ----
    const float MAXOMf = (float)(10000.0 * 2.0 * M_PI);
    const float LOWOMf = (float)(20.0 * 2.0 * M_PI);
    float a1 = __fdiv_rn(__fsub_rn(MAXOMf, omega), 100.0f);
    float a2 = __fdiv_rn(__fsub_rn(omega, LOWOMf), 100.0f);
    float valid = __fmul_rn(sigmoid_of(a1), sigmoid_of(a2));

    // ---- mode shapes (amplitude-only; double cos is plenty) ----
    double PId = (double)PIf;
    float inw = __fmul_rn((float)cos(0.335 * PId * (double)mi),
                          (float)cos((double)yi * PId * (double)nj / (double)Ly));
    float outw = __fmul_rn((float)cos((double)xo * PId * (double)mi),
                           (float)cos((double)yo * PId * (double)nj / (double)Ly));

    float ms = __fmul_rn(__fmul_rn(0.25f, mu), Ly);
    float E  = (float)exp(-(double)__fmul_rn(sigma, KF));
    float P  = __fmul_rn(outw, inw);
    P = __fmul_rn(P, K2F);
    P = __fmul_rn(P, E);
    P = __fdiv_rn(P, ms);
    P = __fmul_rn(P, valid);

    float coef = __fdiv_rn(P, __fadd_rn(sin_acc(theta), 1e-8f));

    g_modes[m] = make_float4(theta, sigma, coef, 0.0f);
}

// ---------------------------------------------------------------------------
// k1: main bank. thread = one output sample t; blockIdx.y = mode chunk.
// Each iteration: bit-exact argument fl((t+1)*theta), accurate sine, __expf
// envelope, one FMA into a register accumulator. Uniform float4 loads.
// ---------------------------------------------------------------------------
__global__ void __launch_bounds__(256) k1_bank(int T) {
    int t = blockIdx.x * blockDim.x + threadIdx.x;
    if (t >= T) return;
    int c = blockIdx.y;

    float tp1 = (float)(t + 1);
    float tK  = __fmul_rn((float)t, KF);     // fl32(n*K)
    float acc = 0.0f;

    int m0 = c * CHUNK;
#pragma unroll 4
    for (int m = m0; m < m0 + CHUNK; ++m) {
        float4 md = g_modes[m];
        float arg = __fmul_rn(tp1, md.x);            // matches ref's f32 rounding
        float s   = sin_acc(arg);
        float e   = __expf(__fmul_rn(-md.y, tK));
        acc = __fmaf_rn(__fmul_rn(md.z, e), s, acc);
    }
    g_part[c][t] = acc;
}

// ---------------------------------------------------------------------------
// k2: first difference / K, track max |ir| via uint atomicMax (vals >= 0)
// ---------------------------------------------------------------------------
__global__ void k2_diff(int T) {
    int t = blockIdx.x * blockDim.x + threadIdx.x;
    if (t >= T) return;
    float d = 0.0f, p = 0.0f;
#pragma unroll
    for (int c = 0; c < NCHUNK; ++c) d += g_part[c][t];
    if (t > 0) {
#pragma unroll
        for (int c = 0; c < NCHUNK; ++c) p += g_part[c][t - 1];
    }
    float ir = __fdiv_rn(__fsub_rn(d, p), KF);
    g_ir[t] = ir;
    atomicMax(&g_maxbits, __float_as_uint(fabsf(ir)));
}

// ---------------------------------------------------------------------------
// k3: peak normalize
// ---------------------------------------------------------------------------
__global__ void k3_norm(int T, float* __restrict__ out) {
    int t = blockIdx.x * blockDim.x + threadIdx.x;
    if (t >= T) return;
    float mx = __uint_as_float(g_maxbits);
    out[t] = __fdiv_rn(g_ir[t], __fadd_rn(mx, 1e-8f));
}

// ---------------------------------------------------------------------------
extern "C" void kernel_launch(void* const* d_in, const int* in_sizes, int n_in,
                              void* d_out, int out_size) {
    (void)in_sizes; (void)n_in;
    const float* mu  = (const float*)d_in[0];
    const float* Dr  = (const float*)d_in[1];
    const float* T0r = (const float*)d_in[2];
    const float* Lyr = (const float*)d_in[3];
    const float* xor_ = (const float*)d_in[4];
    const float* yor_ = (const float*)d_in[5];

    int T = out_size;
    if (T > MAX_T) T = MAX_T;

    k0_setup<<<NMODES / 256, 256>>>(mu, Dr, T0r, Lyr, xor_, yor_);

    dim3 g1((T + 255) / 256, NCHUNK);
    k1_bank<<<g1, 256>>>(T);

    int gb = (T + 255) / 256;
    k2_diff<<<gb, 256>>>(T);
    k3_norm<<<gb, 256>>>(T, (float*)d_out);
}

// round 2
// speedup vs baseline: 2.2710x; 2.2710x over previous
#include <cuda_runtime.h>
#include <math.h>

#define NMODES   6400
#define MDIM     80
#define NCHUNK   128
#define CHUNK    (NMODES / NCHUNK)      /* 50 modes per thread */
#define MAX_T    24576
#define TW       32                     /* samples per thread (stride 32) */

#define KF   ((float)(1.0 / 44100.0))
#define K2F  ((float)((1.0/44100.0)*(1.0/44100.0)))

// per-mode params: A = {theta, sigma, coef, a}, B = {rho32, b}
__device__ float4   g_A[NMODES];
__device__ float2   g_B[NMODES];
__device__ float    g_part[NCHUNK][MAX_T];
__device__ float    g_ir[MAX_T];
__device__ unsigned g_maxbits;

// ---------------------------------------------------------------------------
// Accurate float sine, flag-proof. Cody-Waite 3-term reduction (exact for
// |n| < 2^15), deg-9 minimax poly. Abs error ~3e-6 over needed range.
// ---------------------------------------------------------------------------
__device__ __forceinline__ float sin_acc(float x) {
    const float INV_PI = 0.318309886183790671538f;
    float nf = rintf(__fmul_rn(x, INV_PI));
    int   ni = (int)nf;
    float r = __fmaf_rn(-nf, 3.140625f, x);                     // exact
    r = __fmaf_rn(-nf, 9.670257568359375e-4f, r);               // exact
    r = __fmaf_rn(-nf, 6.2771141529083252e-7f, r);
    float r2 = __fmul_rn(r, r);
    float p  = __fmaf_rn(2.60831598097865935e-06f, r2, -1.98106907191686332e-4f);
    p = __fmaf_rn(p, r2,  8.33307858556509018e-3f);
    p = __fmaf_rn(p, r2, -0.166666597127914429f);
    float s = __fmaf_rn(__fmul_rn(r, r2), p, r);
    // branchless sign flip via XOR (ALU pipe)
    return __int_as_float(__float_as_int(s) ^ ((ni & 1) << 31));
}

__device__ __forceinline__ double softplus_d(double x) {
    return (x > 0.0) ? x + log1p(exp(-x)) : log1p(exp(x));
}
__device__ __forceinline__ float sigmoid_of(float argf) {
    return (float)(1.0 / (1.0 + exp(-(double)argf)));
}

// ---------------------------------------------------------------------------
// k0: per-mode setup (6400 threads). Phase-critical chain in explicit f32 RN.
// Also precomputes stride-32 recurrence coefficients in double.
// ---------------------------------------------------------------------------
__global__ void k0_setup(const float* __restrict__ mu_raw,
                         const float* __restrict__ D_raw,
                         const float* __restrict__ T0_raw,
                         const float* __restrict__ Ly_raw,
                         const float* __restrict__ xo_raw,
                         const float* __restrict__ yo_raw) {
    int m = blockIdx.x * blockDim.x + threadIdx.x;
    if (m == 0) g_maxbits = 0u;
    if (m >= NMODES) return;

    float mu  = __fadd_rn((float)softplus_d((double)*mu_raw),  1e-4f);
    float Dm  = __fadd_rn((float)softplus_d((double)*D_raw),   1e-4f);
    float T0m = __fadd_rn((float)softplus_d((double)*T0_raw),  1e-4f);

    float hLy = __fmul_rn(__fadd_rn((float)tanh((double)*Ly_raw), 1.0f), 0.5f);
    float Ly  = __fadd_rn(1.1f, __fmul_rn(2.9f, hLy));
    float hx  = __fmul_rn(__fadd_rn((float)tanh((double)*xo_raw), 1.0f), 0.5f);
    float xo  = __fadd_rn(0.49f, __fmul_rn(0.51f, hx));
    float hy  = __fmul_rn(__fadd_rn((float)tanh((double)*yo_raw), 1.0f), 0.5f);
    float yo  = __fadd_rn(__fmul_rn(0.51f, Ly), __fmul_rn(__fmul_rn(0.49f, Ly), hy));
    float yi  = __fmul_rn(0.467f, Ly);

    int mi = m / MDIM + 1;
    int nj = m % MDIM + 1;
    const float PIf = (float)M_PI;

    // phase-critical: g1 -> omega -> theta (explicit f32 RN chain)
    float mf = (float)mi, nf = (float)nj;
    float t1 = __fmul_rn(mf, PIf);
    float t2 = __fdiv_rn(__fmul_rn(nf, PIf), Ly);
    float g1 = __fadd_rn(__fmul_rn(t1, t1), __fmul_rn(t2, t2));
    float om_sq = __fadd_rn(__fmul_rn(T0m, g1),
                            __fmul_rn(__fmul_rn(Dm, g1), g1));
    float omega = __fsqrt_rn(fmaxf(om_sq, 0.0f));
    float theta = __fmul_rn(omega, KF);

    const double OM2d   = 2.0 * M_PI * 500.0;
    const double DOMSQd = OM2d * OM2d;
    const double ALPHAd = 3.0 * log(10.0) / DOMSQd * (DOMSQd / 6.0);
    const double BETAd  = 3.0 * log(10.0) / DOMSQd * (1.0 / 2.0 - 1.0 / 6.0);
    float om2f  = __fmul_rn(omega, omega);
    float sigma = __fadd_rn((float)ALPHAd, __fmul_rn((float)BETAd, om2f));

    const float MAXOMf = (float)(10000.0 * 2.0 * M_PI);
    const float LOWOMf = (float)(20.0 * 2.0 * M_PI);
    float a1 = __fdiv_rn(__fsub_rn(MAXOMf, omega), 100.0f);
    float a2 = __fdiv_rn(__fsub_rn(omega, LOWOMf), 100.0f);
    float valid = __fmul_rn(sigmoid_of(a1), sigmoid_of(a2));

    double PId = (double)PIf;
    float inw = __fmul_rn((float)cos(0.335 * PId * (double)mi),
                          (float)cos((double)yi * PId * (double)nj / (double)Ly));
    float outw = __fmul_rn((float)cos((double)xo * PId * (double)mi),
                           (float)cos((double)yo * PId * (double)nj / (double)Ly));

    float ms = __fmul_rn(__fmul_rn(0.25f, mu), Ly);
    float E  = (float)exp(-(double)__fmul_rn(sigma, KF));
    float P  = __fmul_rn(outw, inw);
    P = __fmul_rn(P, K2F);
    P = __fmul_rn(P, E);
    P = __fdiv_rn(P, ms);
    P = __fmul_rn(P, valid);

    float coef = __fdiv_rn(P, __fadd_rn(sin_acc(theta), 1e-8f));

    // stride-32 damped recurrence coefficients (double precision)
    double sd   = (double)sigma;
    double Kd   = 1.0 / 44100.0;
    double r32d = exp(-32.0 * sd * Kd);
    double Thd  = 32.0 * (double)theta;
    float  a    = (float)(2.0 * r32d * cos(Thd));
    float  b    = (float)(-(r32d * r32d));

    g_A[m] = make_float4(theta, sigma, coef, a);
    g_B[m] = make_float2((float)r32d, b);
}

// ---------------------------------------------------------------------------
// k1: modal bank via damped Chebyshev recurrence, stride 32.
// Thread owns samples { base + 32*j : j=0..31 }, base = warp_t*1024 + lane.
// Exact re-init per tile (2 accurate sines + exp) bounds recurrence error.
// blockIdx.y = mode chunk (50 modes).
// ---------------------------------------------------------------------------
__global__ void __launch_bounds__(256) k1_bank(int T) {
    int gtid   = blockIdx.x * blockDim.x + threadIdx.x;
    int warp_t = gtid >> 5;
    int lane   = threadIdx.x & 31;
    int base   = warp_t * (32 * TW) + lane;
    if (base >= T) return;
    int c = blockIdx.y;

    float acc[TW];
#pragma unroll
    for (int j = 0; j < TW; ++j) acc[j] = 0.0f;

    float tp0 = (float)(base + 1);                  // (n+1) for j=0
    float tp1 = (float)(base + 33);                 // (n+1) for j=1
    float nk0 = __fmul_rn((float)base, KF);         // fl(n0*K)

    int m0 = c * CHUNK;
    for (int m = m0; m < m0 + CHUNK; ++m) {
        float4 A = g_A[m];
        float2 B = g_B[m];
        float th = A.x, sg = A.y, C = A.z, a = A.w;
        float r32 = B.x, b = B.y;

        float s0 = sin_acc(__fmul_rn(tp0, th));
        float s1 = sin_acc(__fmul_rn(tp1, th));
        float e0 = __expf(-__fmul_rn(sg, nk0));
        float e1 = __fmul_rn(e0, r32);
        float v0 = __fmul_rn(e0, s0);
        float v1 = __fmul_rn(e1, s1);
        acc[0] = __fmaf_rn(C, v0, acc[0]);
        acc[1] = __fmaf_rn(C, v1, acc[1]);

#pragma unroll
        for (int j = 2; j < TW; ++j) {
            float v2 = __fmaf_rn(a, v1, __fmul_rn(b, v0));
            acc[j] = __fmaf_rn(C, v2, acc[j]);
            v0 = v1; v1 = v2;
        }
    }

#pragma unroll
    for (int j = 0; j < TW; ++j) {
        int t = base + 32 * j;
        if (t < T) g_part[c][t] = acc[j];
    }
}

// ---------------------------------------------------------------------------
// k2: sum chunks, first difference / K, track max|ir| (uint atomicMax)
// ---------------------------------------------------------------------------
__global__ void k2_diff(int T) {
    __shared__ float sm[257];
    int t = blockIdx.x * blockDim.x + threadIdx.x;

    float s = 0.0f;
    if (t < T) {
#pragma unroll 8
        for (int c = 0; c < NCHUNK; ++c) s += g_part[c][t];
    }
    sm[threadIdx.x + 1] = s;
    if (threadIdx.x == 0) {
        float p = 0.0f;
        int tp = (int)(blockIdx.x * blockDim.x) - 1;
        if (tp >= 0 && tp < T) {
            for (int c = 0; c < NCHUNK; ++c) p += g_part[c][tp];
        }
        sm[0] = p;
    }
    __syncthreads();
    if (t >= T) return;

    float prev = (t == 0) ? 0.0f : sm[threadIdx.x];
    float ir = __fdiv_rn(__fsub_rn(s, prev), KF);
    g_ir[t] = ir;
    atomicMax(&g_maxbits, __float_as_uint(fabsf(ir)));
}

// ---------------------------------------------------------------------------
// k3: peak normalize
// ---------------------------------------------------------------------------
__global__ void k3_norm(int T, float* __restrict__ out) {
    int t = blockIdx.x * blockDim.x + threadIdx.x;
    if (t >= T) return;
    float mx = __uint_as_float(g_maxbits);
    out[t] = __fdiv_rn(g_ir[t], __fadd_rn(mx, 1e-8f));
}

// ---------------------------------------------------------------------------
extern "C" void kernel_launch(void* const* d_in, const int* in_sizes, int n_in,
                              void* d_out, int out_size) {
    (void)in_sizes; (void)n_in;
    const float* mu   = (const float*)d_in[0];
    const float* Dr   = (const float*)d_in[1];
    const float* T0r  = (const float*)d_in[2];
    const float* Lyr  = (const float*)d_in[3];
    const float* xor_ = (const float*)d_in[4];
    const float* yor_ = (const float*)d_in[5];

    int T = out_size;
    if (T > MAX_T) T = MAX_T;

    k0_setup<<<NMODES / 256, 256>>>(mu, Dr, T0r, Lyr, xor_, yor_);

    int warps_t  = (T + 32 * TW - 1) / (32 * TW);       // 1024-sample warp tiles
    int blocks_x = (warps_t + 7) / 8;                   // 8 warps per block
    dim3 g1(blocks_x, NCHUNK);
    k1_bank<<<g1, 256>>>(T);

    int gb = (T + 255) / 256;
    k2_diff<<<gb, 256>>>(T);
    k3_norm<<<gb, 256>>>(T, (float*)d_out);
}